// round 9
// baseline (speedup 1.0000x reference)
#include <cuda_runtime.h>
#include <cuda_bf16.h>
#include <cuda_fp16.h>
#include <cstdint>

// ---------------------------------------------------------------------------
// TransformerBlock N=32768, IN=512, HID=512, HEAD=4  (mma.sync path)
//   M_h  = Wq_h^T @ Wk_h ;  P^T_h = Wc_h^T @ Wv_h^T      (tiny precompute)
//   att[n,h] = x_n . (ih @ M_h^T)_n                      (fused epilogue)
//   alpha = softmax over nodes; y = x @ P
//   h1 = LN( sum_h alpha[n,h]*y_h[n] + x )               (fused)
//   out = LN( relu(h1@W1+b1)@W2+b2 + h1 )
// Attention branch: single-product bf16 (branch is O(1e-5) of output).
// FFN: 2-product fp16 (activation hi/lo, weights rounded to fp16).
// ---------------------------------------------------------------------------
#define NN 32768
#define ATT_SCALE 0.044194173824159216f

// ---- scratch ----------------------------------------------------------------
__device__ __nv_bfloat16 g_xh[(size_t)NN * 512];
__device__ __nv_bfloat16 g_ihh[(size_t)NN * 512];
__device__ __nv_bfloat16 g_wth[5242880], g_wtl[5242880];  // weight planes (16-bit slots)
__device__ __nv_bfloat16 g_wM[2048 * 512];                // M:  [h*512+i][j]
__device__ __nv_bfloat16 g_wP[2048 * 512];                // P^T:[h*512+o][d]
__device__ __nv_bfloat16 g_y[(size_t)NN * 2048];          // x @ P  (head-major)
__device__ float g_f2[(size_t)NN * 512];
__device__ __half g_h1h[(size_t)NN * 512],  g_h1l[(size_t)NN * 512];
__device__ __half g_f1h[(size_t)NN * 1024], g_f1l[(size_t)NN * 1024];
__device__ float g_att[NN * 4];
__device__ float g_denom[4];

#define WOFF_Q  0           // Wq^T  [4][512 i][512 d]   bf16
#define WOFF_K  1048576     // Wk^T  [4][512 j][512 d]   bf16
#define WOFF_V  2097152     // Wv (plain) [4][512 d][512 c] bf16
#define WOFF_C  3145728     // Wc^T  [512 o][2048 c]     bf16
#define WOFF_1  4194304     // W1^T  [1024][512]         fp16
#define WOFF_2  4718592     // W2^T  [512][1024]         fp16

// ---- PTX helpers ------------------------------------------------------------
__device__ __forceinline__ uint32_t smem_u32(const void* p) {
    uint32_t a;
    asm("{ .reg .u64 t; cvta.to.shared.u64 t, %1; cvt.u32.u64 %0, t; }" : "=r"(a) : "l"(p));
    return a;
}
__device__ __forceinline__ void cp16(uint32_t dst, const void* src) {
    asm volatile("cp.async.ca.shared.global [%0], [%1], 16;" :: "r"(dst), "l"(src));
}
__device__ __forceinline__ void cp_commit() {
    asm volatile("cp.async.commit_group;" ::: "memory");
}
template <int N>
__device__ __forceinline__ void cp_wait() {
    asm volatile("cp.async.wait_group %0;" :: "n"(N) : "memory");
}
__device__ __forceinline__ void ldsm4(uint32_t& r0, uint32_t& r1, uint32_t& r2, uint32_t& r3,
                                      uint32_t addr) {
    asm volatile("ldmatrix.sync.aligned.m8n8.x4.shared.b16 {%0,%1,%2,%3}, [%4];"
                 : "=r"(r0), "=r"(r1), "=r"(r2), "=r"(r3) : "r"(addr));
}
template <int DT>  // 0 = bf16, 1 = fp16
__device__ __forceinline__ void mma16816(float* d, const uint32_t* a, const uint32_t* b) {
    if (DT == 0)
        asm volatile(
            "mma.sync.aligned.m16n8k16.row.col.f32.bf16.bf16.f32 "
            "{%0,%1,%2,%3}, {%4,%5,%6,%7}, {%8,%9}, {%0,%1,%2,%3};"
            : "+f"(d[0]), "+f"(d[1]), "+f"(d[2]), "+f"(d[3])
            : "r"(a[0]), "r"(a[1]), "r"(a[2]), "r"(a[3]), "r"(b[0]), "r"(b[1]));
    else
        asm volatile(
            "mma.sync.aligned.m16n8k16.row.col.f32.f16.f16.f32 "
            "{%0,%1,%2,%3}, {%4,%5,%6,%7}, {%8,%9}, {%0,%1,%2,%3};"
            : "+f"(d[0]), "+f"(d[1]), "+f"(d[2]), "+f"(d[3])
            : "r"(a[0]), "r"(a[1]), "r"(a[2]), "r"(a[3]), "r"(b[0]), "r"(b[1]));
}
__device__ __forceinline__ void bsplit(float v, __nv_bfloat16& h, __nv_bfloat16& l) {
    h = __float2bfloat16(v);
    l = __float2bfloat16(v - __bfloat162float(h));
}
__device__ __forceinline__ void hsplit(float v, __half& h, __half& l) {
    h = __float2half_rn(v);
    l = __float2half_rn(v - __half2float(h));
}

// ---- selectors ----------------------------------------------------------------
__device__ __forceinline__ void pickA(int s, long long off,
                                      const __nv_bfloat16*& h, const __nv_bfloat16*& l) {
    switch (s) {
        case 0: h = g_xh;  l = nullptr; break;
        case 1: h = g_ihh; l = nullptr; break;
        case 2: h = (const __nv_bfloat16*)g_h1h; l = (const __nv_bfloat16*)g_h1l; break;
        case 3: h = (const __nv_bfloat16*)g_f1h; l = (const __nv_bfloat16*)g_f1l; break;
        default: h = g_wth + off; l = g_wtl + off; return;
    }
}
__device__ __forceinline__ void pickB(int s, long long off,
                                      const __nv_bfloat16*& h) {
    switch (s) {
        case 0: h = g_wth + off; break;
        case 1: h = g_wM; break;
        default: h = g_wP; break;
    }
}
__device__ __forceinline__ __nv_bfloat16* pickCb(int s) {
    switch (s) { case 0: return g_y; case 1: return g_wM; default: return g_wP; }
}

// ---------------------------------------------------------------------------
// GEMM: C[M,Ntot] = A[M,K] @ B[Ntot,K]^T via mma.sync m16n8k16
//   CTA 128x128, 8 warps (2m x 4n), warp tile 64x32, K chunk 32, 3 stages.
//   PROD: 1 = Ah*Bh ; 2 = Ah*Bh + Al*Bh (activation-compensated)
//   EPI:  0 bf16 store | 2 f32+bias->g_f2 | 3 bias+relu->f1 fp16 planes | 4 att-dot
//   DT:   0 bf16, 1 fp16
// ---------------------------------------------------------------------------
#define PITCH 80

template <int PROD, int EPI, int DT>
__global__ __launch_bounds__(256, 2) void mma_gemm(
    int aSel, long long aOff, int lda, long long aZ,
    int bSel, long long bOff, long long bZ,
    int K, int cSel, long long cZ, int ldc,
    const float* __restrict__ bias)
{
    constexpr int PLANE  = 10240;
    constexpr int OFF_AL = PLANE;                          // PROD2 only
    constexpr int OFF_B  = (PROD == 1) ? PLANE : 2 * PLANE;
    constexpr int STAGE  = (PROD == 1) ? 2 * PLANE : 3 * PLANE;

    extern __shared__ char dsm[];
    const uint32_t sb = smem_u32(dsm);

    const int tid = threadIdx.x;
    const int lane = tid & 31;
    const int wid = tid >> 5;
    const int wm = wid & 1;
    const int wn = wid >> 1;

    const __nv_bfloat16 *Ah, *Al, *Bh;
    pickA(aSel, aOff + (long long)blockIdx.z * aZ, Ah, Al);
    pickB(bSel, bOff + (long long)blockIdx.z * bZ, Bh);

    const size_t mbase = (size_t)blockIdx.y * 128;
    const int nbase = blockIdx.x * 128;

    const int r0s = tid >> 2;
    const int seg = tid & 3;

    float acc[4][4][4];
#pragma unroll
    for (int i = 0; i < 4; i++)
#pragma unroll
        for (int j = 0; j < 4; j++)
#pragma unroll
            for (int q = 0; q < 4; q++) acc[i][j][q] = 0.f;

    const int nch = K >> 5;

    auto load_chunk = [&](int c, int stg) {
        const int kOff = c << 5;
        const uint32_t base = sb + stg * STAGE;
#pragma unroll
        for (int it = 0; it < 2; it++) {
            const int row = r0s + it * 64;
            const uint32_t d = base + row * PITCH + seg * 16;
            const size_t gA = (mbase + row) * (size_t)lda + kOff + seg * 8;
            const size_t gB = ((size_t)nbase + row) * (size_t)K + kOff + seg * 8;
            cp16(d, Ah + gA);
            cp16(d + OFF_B, Bh + gB);
            if (PROD == 2) cp16(d + OFF_AL, Al + gA);
        }
        cp_commit();
    };

    // 3-stage prologue
    load_chunk(0, 0);
    load_chunk(1, 1);

    int stg = 0, stg2 = 2;                 // stage of chunk c, and of chunk c+2
    for (int c = 0; c < nch; c++) {
        cp_wait<1>();                      // chunk c resident
        __syncthreads();                   // all warps done with stage (c-1)%3
        if (c + 2 < nch) load_chunk(c + 2, stg2);
        else             cp_commit();      // keep group accounting aligned

        const uint32_t sA = sb + stg * STAGE;
#pragma unroll
        for (int ks = 0; ks < 2; ks++) {
            const uint32_t colA = ks * 32 + ((lane >> 4) << 4);
            const uint32_t colB = ks * 32 + (((lane >> 3) & 1) << 4);

            uint32_t aH[4][4], bH[2][4];
            uint32_t aL[4][4];
#pragma unroll
            for (int mt = 0; mt < 4; mt++) {
                const uint32_t ad = sA + (wm * 64 + mt * 16 + (lane & 15)) * PITCH + colA;
                ldsm4(aH[mt][0], aH[mt][1], aH[mt][2], aH[mt][3], ad);
                if (PROD == 2)
                    ldsm4(aL[mt][0], aL[mt][1], aL[mt][2], aL[mt][3], ad + OFF_AL);
            }
#pragma unroll
            for (int nt2 = 0; nt2 < 2; nt2++) {
                const uint32_t bd = sA + OFF_B +
                    (wn * 32 + nt2 * 16 + (lane & 7) + ((lane >> 4) << 3)) * PITCH + colB;
                ldsm4(bH[nt2][0], bH[nt2][1], bH[nt2][2], bH[nt2][3], bd);
            }
#pragma unroll
            for (int mt = 0; mt < 4; mt++)
#pragma unroll
                for (int nt = 0; nt < 4; nt++) {
                    const uint32_t* bh = &bH[nt >> 1][(nt & 1) * 2];
                    mma16816<DT>(acc[mt][nt], aH[mt], bh);
                    if (PROD == 2) mma16816<DT>(acc[mt][nt], aL[mt], bh);
                }
        }
        stg = (stg == 2) ? 0 : stg + 1;
        stg2 = (stg2 == 2) ? 0 : stg2 + 1;
    }

    // ---- epilogues ----
    if (EPI == 4) {
        // att[n,h] += x[n,:] . t[n,:] over this tile's cols;  h = nbase>>9
        const int h = nbase >> 9;
#pragma unroll
        for (int mt = 0; mt < 4; mt++) {
            const size_t r = mbase + wm * 64 + mt * 16 + (lane >> 2);
            float p0 = 0.f, p1 = 0.f;
#pragma unroll
            for (int nt = 0; nt < 4; nt++) {
                const int col = nbase + wn * 32 + nt * 8 + ((lane & 3) << 1);
                const int i = col & 511;
                float2 x0 = __bfloat1622float2(*(const __nv_bfloat162*)(g_xh + r * 512 + i));
                float2 x1 = __bfloat1622float2(*(const __nv_bfloat162*)(g_xh + (r + 8) * 512 + i));
                p0 = fmaf(acc[mt][nt][0], x0.x, p0);
                p0 = fmaf(acc[mt][nt][1], x0.y, p0);
                p1 = fmaf(acc[mt][nt][2], x1.x, p1);
                p1 = fmaf(acc[mt][nt][3], x1.y, p1);
            }
            p0 += __shfl_xor_sync(0xffffffffu, p0, 1);
            p0 += __shfl_xor_sync(0xffffffffu, p0, 2);
            p1 += __shfl_xor_sync(0xffffffffu, p1, 1);
            p1 += __shfl_xor_sync(0xffffffffu, p1, 2);
            if ((lane & 3) == 0) {
                atomicAdd(&g_att[r * 4 + h], p0);
                atomicAdd(&g_att[(r + 8) * 4 + h], p1);
            }
        }
        return;
    }

    __nv_bfloat16* Cb = (EPI == 0) ? pickCb(cSel) + (size_t)blockIdx.z * cZ : nullptr;

#pragma unroll
    for (int mt = 0; mt < 4; mt++) {
        const size_t row = mbase + wm * 64 + mt * 16 + (lane >> 2);
#pragma unroll
        for (int nt = 0; nt < 4; nt++) {
            const int col = nbase + wn * 32 + nt * 8 + ((lane & 3) << 1);
            float v0 = acc[mt][nt][0], v1 = acc[mt][nt][1];
            float v2 = acc[mt][nt][2], v3 = acc[mt][nt][3];
            if (EPI >= 2) {
                const float bb0 = bias[col], bb1 = bias[col + 1];
                v0 += bb0; v1 += bb1; v2 += bb0; v3 += bb1;
            }
            if (EPI == 3) {
                v0 = fmaxf(v0, 0.f); v1 = fmaxf(v1, 0.f);
                v2 = fmaxf(v2, 0.f); v3 = fmaxf(v3, 0.f);
                __half h0, h1, l0, l1;
                __half2 ph, pl;
                size_t o = row * (size_t)ldc + col;
                hsplit(v0, h0, l0); hsplit(v1, h1, l1);
                ph.x = h0; ph.y = h1; pl.x = l0; pl.y = l1;
                *(__half2*)(g_f1h + o) = ph;
                *(__half2*)(g_f1l + o) = pl;
                o = (row + 8) * (size_t)ldc + col;
                hsplit(v2, h0, l0); hsplit(v3, h1, l1);
                ph.x = h0; ph.y = h1; pl.x = l0; pl.y = l1;
                *(__half2*)(g_f1h + o) = ph;
                *(__half2*)(g_f1l + o) = pl;
            } else if (EPI == 0) {
                __nv_bfloat162 p;
                p.x = __float2bfloat16(v0); p.y = __float2bfloat16(v1);
                *(__nv_bfloat162*)(Cb + row * (size_t)ldc + col) = p;
                p.x = __float2bfloat16(v2); p.y = __float2bfloat16(v3);
                *(__nv_bfloat162*)(Cb + (row + 8) * (size_t)ldc + col) = p;
            } else {  // EPI == 2
                float2 p;
                p.x = v0; p.y = v1;
                *(float2*)(g_f2 + row * (size_t)ldc + col) = p;
                p.x = v2; p.y = v3;
                *(float2*)(g_f2 + (row + 8) * (size_t)ldc + col) = p;
            }
        }
    }
}

// ---------------------------------------------------------------------------
// aux kernels
// ---------------------------------------------------------------------------
__global__ void split_in_kernel(const float* __restrict__ src, int dsel) {
    __nv_bfloat16* dh = dsel ? g_ihh : g_xh;
    const size_t i = (size_t)blockIdx.x * blockDim.x + threadIdx.x;
    const float4 v = ((const float4*)src)[i];
    __nv_bfloat162 a, b;
    a.x = __float2bfloat16(v.x); a.y = __float2bfloat16(v.y);
    b.x = __float2bfloat16(v.z); b.y = __float2bfloat16(v.w);
    *((__nv_bfloat162*)(dh + 4 * i)) = a;
    *((__nv_bfloat162*)(dh + 4 * i + 2)) = b;
}

__global__ void conv_w_kernel(const float* __restrict__ src, long long dstOff) {
    const size_t i = (size_t)blockIdx.x * blockDim.x + threadIdx.x;
    const float4 v = ((const float4*)src)[i];
    __nv_bfloat16* dh = g_wth + dstOff;
    __nv_bfloat162 a, b;
    a.x = __float2bfloat16(v.x); a.y = __float2bfloat16(v.y);
    b.x = __float2bfloat16(v.z); b.y = __float2bfloat16(v.w);
    *((__nv_bfloat162*)(dh + 4 * i)) = a;
    *((__nv_bfloat162*)(dh + 4 * i + 2)) = b;
}

// transpose: fp32 [K][Nn] -> 16-bit planes [Nn][K]; mode 0 = bf16 hi/lo, 1 = fp16 hi
__global__ void tsplit_kernel(const float* __restrict__ src, int K, int Nn,
                              long long srcZ, long long dstOff, long long dstZ,
                              int fp16mode) {
    __shared__ float t[32][33];
    const float* s = src + (size_t)blockIdx.z * srcZ;
    const size_t dbase = (size_t)dstOff + (size_t)blockIdx.z * dstZ;
    const int k0 = blockIdx.x * 32, n0 = blockIdx.y * 32;
    const int tx = threadIdx.x, ty = threadIdx.y;
    for (int r = ty; r < 32; r += 8)
        t[r][tx] = s[(size_t)(k0 + r) * Nn + n0 + tx];
    __syncthreads();
    for (int r = ty; r < 32; r += 8) {
        const float v = t[tx][r];
        const size_t o = dbase + (size_t)(n0 + r) * K + k0 + tx;
        if (fp16mode) {
            ((__half*)g_wth)[o] = __float2half_rn(v);
        } else {
            __nv_bfloat16 h, l;
            bsplit(v, h, l);
            g_wth[o] = h;
            g_wtl[o] = l;
        }
    }
}

__global__ void zero_att_kernel() {
    const size_t i = (size_t)blockIdx.x * blockDim.x + threadIdx.x;
    ((float4*)g_att)[i] = make_float4(0.f, 0.f, 0.f, 0.f);
    if (blockIdx.x == 0 && threadIdx.x < 4) g_denom[threadIdx.x] = 0.f;
}

__global__ void denom_kernel() {
    const int idx = blockIdx.x * blockDim.x + threadIdx.x;
    const float4 v = *(const float4*)(g_att + (size_t)idx * 4);
    float e0 = expf(v.x * ATT_SCALE), e1 = expf(v.y * ATT_SCALE);
    float e2 = expf(v.z * ATT_SCALE), e3 = expf(v.w * ATT_SCALE);
#pragma unroll
    for (int o = 16; o; o >>= 1) {
        e0 += __shfl_down_sync(0xffffffffu, e0, o);
        e1 += __shfl_down_sync(0xffffffffu, e1, o);
        e2 += __shfl_down_sync(0xffffffffu, e2, o);
        e3 += __shfl_down_sync(0xffffffffu, e3, o);
    }
    __shared__ float sm[4][8];
    const int w = threadIdx.x >> 5, lane = threadIdx.x & 31;
    if (lane == 0) { sm[0][w] = e0; sm[1][w] = e1; sm[2][w] = e2; sm[3][w] = e3; }
    __syncthreads();
    if (threadIdx.x < 4) {
        float s = 0.f;
#pragma unroll
        for (int i = 0; i < 8; i++) s += sm[threadIdx.x][i];
        atomicAdd(&g_denom[threadIdx.x], s);
    }
}

// h1 = LN( sum_h alpha[n,h]*y[n,h*512+o] + x[n,o] ); writes fp16 hi/lo planes
__global__ void ln1_fused(const float* __restrict__ x,
                          const float* __restrict__ gam,
                          const float* __restrict__ bet) {
    const int n = blockIdx.x;
    const int t = threadIdx.x;
    const size_t xb = (size_t)n * 512;
    const size_t yb = (size_t)n * 2048;

    float alpha[4];
#pragma unroll
    for (int h = 0; h < 4; h++)
        alpha[h] = expf(g_att[n * 4 + h] * ATT_SCALE) / g_denom[h];

    float mo0 = 0.f, mo1 = 0.f;
#pragma unroll
    for (int h = 0; h < 4; h++) {
        mo0 = fmaf(alpha[h], __bfloat162float(g_y[yb + h * 512 + t]), mo0);
        mo1 = fmaf(alpha[h], __bfloat162float(g_y[yb + h * 512 + t + 256]), mo1);
    }
    const float v0 = mo0 + x[xb + t];
    const float v1 = mo1 + x[xb + t + 256];

    float s = v0 + v1, q = v0 * v0 + v1 * v1;
#pragma unroll
    for (int o = 16; o; o >>= 1) {
        s += __shfl_down_sync(0xffffffffu, s, o);
        q += __shfl_down_sync(0xffffffffu, q, o);
    }
    __shared__ float ss[8], qq[8];
    __shared__ float s_mean, s_rstd;
    const int w = t >> 5, lane = t & 31;
    if (lane == 0) { ss[w] = s; qq[w] = q; }
    __syncthreads();
    if (t == 0) {
        float S = 0.f, Q2 = 0.f;
#pragma unroll
        for (int i = 0; i < 8; i++) { S += ss[i]; Q2 += qq[i]; }
        const float mean = S * (1.0f / 512.0f);
        s_mean = mean;
        s_rstd = rsqrtf(Q2 * (1.0f / 512.0f) - mean * mean + 1e-5f);
    }
    __syncthreads();
    const float mean = s_mean, r = s_rstd;
    const float o0 = (v0 - mean) * r * gam[t] + bet[t];
    const float o1 = (v1 - mean) * r * gam[t + 256] + bet[t + 256];
    __half h, l;
    hsplit(o0, h, l); g_h1h[xb + t] = h;       g_h1l[xb + t] = l;
    hsplit(o1, h, l); g_h1h[xb + t + 256] = h; g_h1l[xb + t + 256] = l;
}

// out = LN(f2 + h1), h1 reconstructed from fp16 hi+lo planes
__global__ void ln2_kernel(const float* __restrict__ gam,
                           const float* __restrict__ bet,
                           float* __restrict__ out) {
    const int n = blockIdx.x;
    const int t = threadIdx.x;
    const size_t base = (size_t)n * 512;
    const float h10 = __half2float(g_h1h[base + t]) + __half2float(g_h1l[base + t]);
    const float h11 = __half2float(g_h1h[base + t + 256]) + __half2float(g_h1l[base + t + 256]);
    const float v0 = g_f2[base + t] + h10;
    const float v1 = g_f2[base + t + 256] + h11;
    float s = v0 + v1, q = v0 * v0 + v1 * v1;
#pragma unroll
    for (int o = 16; o; o >>= 1) {
        s += __shfl_down_sync(0xffffffffu, s, o);
        q += __shfl_down_sync(0xffffffffu, q, o);
    }
    __shared__ float ss[8], qq[8];
    __shared__ float s_mean, s_rstd;
    const int w = t >> 5, lane = t & 31;
    if (lane == 0) { ss[w] = s; qq[w] = q; }
    __syncthreads();
    if (t == 0) {
        float S = 0.f, Q2 = 0.f;
#pragma unroll
        for (int i = 0; i < 8; i++) { S += ss[i]; Q2 += qq[i]; }
        const float mean = S * (1.0f / 512.0f);
        s_mean = mean;
        s_rstd = rsqrtf(Q2 * (1.0f / 512.0f) - mean * mean + 1e-5f);
    }
    __syncthreads();
    const float mean = s_mean, r = s_rstd;
    out[base + t]       = (v0 - mean) * r * gam[t]       + bet[t];
    out[base + t + 256] = (v1 - mean) * r * gam[t + 256] + bet[t + 256];
}

// ---------------------------------------------------------------------------
#define SMEM_P1 61440    // 3 stages x 2 planes
#define SMEM_P2 92160    // 3 stages x 3 planes

extern "C" void kernel_launch(void* const* d_in, const int* in_sizes, int n_in,
                              void* d_out, int out_size) {
    (void)in_sizes; (void)n_in; (void)out_size;
    const float* x   = (const float*)d_in[0];
    const float* ih  = (const float*)d_in[1];
    const float* Wq  = (const float*)d_in[4];
    const float* Wk  = (const float*)d_in[5];
    const float* Wv  = (const float*)d_in[6];
    const float* Wc  = (const float*)d_in[7];
    const float* W1  = (const float*)d_in[8];
    const float* b1  = (const float*)d_in[9];
    const float* W2  = (const float*)d_in[10];
    const float* b2  = (const float*)d_in[11];
    const float* lng = (const float*)d_in[12];
    const float* lnb = (const float*)d_in[13];
    float* out = (float*)d_out;

    cudaFuncSetAttribute(mma_gemm<1, 0, 0>, cudaFuncAttributeMaxDynamicSharedMemorySize, SMEM_P1);
    cudaFuncSetAttribute(mma_gemm<1, 4, 0>, cudaFuncAttributeMaxDynamicSharedMemorySize, SMEM_P1);
    cudaFuncSetAttribute(mma_gemm<2, 3, 1>, cudaFuncAttributeMaxDynamicSharedMemorySize, SMEM_P2);
    cudaFuncSetAttribute(mma_gemm<2, 2, 1>, cudaFuncAttributeMaxDynamicSharedMemorySize, SMEM_P2);

    const dim3 tb(32, 8);

    // weight prep
    tsplit_kernel<<<dim3(16, 16, 4), tb>>>(Wq, 512, 512, 262144, WOFF_Q, 262144, 0);
    tsplit_kernel<<<dim3(16, 16, 4), tb>>>(Wk, 512, 512, 262144, WOFF_K, 262144, 0);
    conv_w_kernel<<<1024, 256>>>(Wv, WOFF_V);
    tsplit_kernel<<<dim3(64, 16, 1), tb>>>(Wc, 2048, 512, 0, WOFF_C, 0, 0);
    tsplit_kernel<<<dim3(16, 32, 1), tb>>>(W1, 512, 1024, 0, WOFF_1, 0, 1);
    tsplit_kernel<<<dim3(32, 16, 1), tb>>>(W2, 1024, 512, 0, WOFF_2, 0, 1);

    split_in_kernel<<<16384, 256>>>(x, 0);
    split_in_kernel<<<16384, 256>>>(ih, 1);
    zero_att_kernel<<<128, 256>>>();

    // M_h = Wq_h^T @ Wk_h  -> g_wM
    mma_gemm<1, 0, 0><<<dim3(4, 4, 4), 256, SMEM_P1>>>(
        4, WOFF_Q, 512, 262144, 0, WOFF_K, 262144, 512, 1, 262144, 512, nullptr);
    // P^T_h = Wc_h^T @ Wv_h^T -> g_wP
    mma_gemm<1, 0, 0><<<dim3(4, 4, 4), 256, SMEM_P1>>>(
        4, WOFF_C, 2048, 512, 0, WOFF_V, 262144, 512, 2, 262144, 512, nullptr);

    // t = ih @ M^T with fused att-dot epilogue
    mma_gemm<1, 4, 0><<<dim3(16, 256), 256, SMEM_P1>>>(
        1, 0, 512, 0, 1, 0, 0, 512, 0, 0, 0, nullptr);
    denom_kernel<<<128, 256>>>();

    // y = x @ P -> g_y bf16 [N,2048]
    mma_gemm<1, 0, 0><<<dim3(16, 256), 256, SMEM_P1>>>(
        0, 0, 512, 0, 2, 0, 0, 512, 0, 0, 2048, nullptr);

    // h1 = LN(sum_h alpha*y + x) -> fp16 planes
    ln1_fused<<<NN, 256>>>(x, lng, lnb);

    // f1 = relu(h1 @ W1 + b1) -> fp16 planes   (2-product fp16)
    mma_gemm<2, 3, 1><<<dim3(8, 256), 256, SMEM_P2>>>(
        2, 0, 512, 0, 0, WOFF_1, 0, 512, 0, 0, 1024, b1);
    // f2 = f1 @ W2 + b2 -> f32
    mma_gemm<2, 2, 1><<<dim3(4, 256), 256, SMEM_P2>>>(
        3, 0, 1024, 0, 0, WOFF_2, 0, 1024, 0, 0, 512, b2);

    ln2_kernel<<<NN, 256>>>(lng, lnb, out);
}

// round 10
// speedup vs baseline: 1.0052x; 1.0052x over previous
#include <cuda_runtime.h>
#include <cuda_bf16.h>
#include <cuda_fp16.h>
#include <cstdint>

// ---------------------------------------------------------------------------
// TransformerBlock N=32768, IN=512, HID=512, HEAD=4  (mma.sync path)
//   M_h  = Wq_h^T @ Wk_h ;  P^T_h = Wc_h^T @ Wv_h^T      (tiny precompute)
//   att[n,h] = x_n . (ih @ M_h^T)_n                      (fused epilogue)
//   alpha = softmax over nodes; y = x @ P
//   h1 = LN( sum_h alpha[n,h]*y_h[n] + x )               (fused)
//   out = LN( relu(h1@W1+b1)@W2+b2 + h1 )
// Attention branch: single-product bf16 (branch is O(1e-5) of output).
// FFN: 2-product fp16 (activation hi/lo, weights rounded to fp16).
// ---------------------------------------------------------------------------
#define NN 32768
#define ATT_SCALE 0.044194173824159216f

// ---- scratch ----------------------------------------------------------------
__device__ __nv_bfloat16 g_xh[(size_t)NN * 512];
__device__ __nv_bfloat16 g_ihh[(size_t)NN * 512];
__device__ __nv_bfloat16 g_wth[5242880], g_wtl[5242880];  // weight planes (16-bit slots)
__device__ __nv_bfloat16 g_wM[2048 * 512];                // M:  [h*512+i][j]
__device__ __nv_bfloat16 g_wP[2048 * 512];                // P^T:[h*512+o][d]
__device__ __nv_bfloat16 g_y[(size_t)NN * 2048];          // x @ P  (head-major)
__device__ float g_f2[(size_t)NN * 512];
__device__ __half g_h1h[(size_t)NN * 512],  g_h1l[(size_t)NN * 512];
__device__ __half g_f1h[(size_t)NN * 1024], g_f1l[(size_t)NN * 1024];
__device__ float g_att[NN * 4];
__device__ float g_denom[4];

#define WOFF_Q  0           // Wq^T  [4][512 i][512 d]   bf16
#define WOFF_K  1048576     // Wk^T  [4][512 j][512 d]   bf16
#define WOFF_V  2097152     // Wv (plain) [4][512 d][512 c] bf16
#define WOFF_C  3145728     // Wc^T  [512 o][2048 c]     bf16
#define WOFF_1  4194304     // W1^T  [1024][512]         fp16
#define WOFF_2  4718592     // W2^T  [512][1024]         fp16

// ---- PTX helpers ------------------------------------------------------------
__device__ __forceinline__ uint32_t smem_u32(const void* p) {
    uint32_t a;
    asm("{ .reg .u64 t; cvta.to.shared.u64 t, %1; cvt.u32.u64 %0, t; }" : "=r"(a) : "l"(p));
    return a;
}
__device__ __forceinline__ void cp16(uint32_t dst, const void* src) {
    asm volatile("cp.async.ca.shared.global [%0], [%1], 16;" :: "r"(dst), "l"(src));
}
__device__ __forceinline__ void cp_commit() {
    asm volatile("cp.async.commit_group;" ::: "memory");
}
template <int N>
__device__ __forceinline__ void cp_wait() {
    asm volatile("cp.async.wait_group %0;" :: "n"(N) : "memory");
}
__device__ __forceinline__ void ldsm4(uint32_t& r0, uint32_t& r1, uint32_t& r2, uint32_t& r3,
                                      uint32_t addr) {
    asm volatile("ldmatrix.sync.aligned.m8n8.x4.shared.b16 {%0,%1,%2,%3}, [%4];"
                 : "=r"(r0), "=r"(r1), "=r"(r2), "=r"(r3) : "r"(addr));
}
template <int DT>  // 0 = bf16, 1 = fp16
__device__ __forceinline__ void mma16816(float* d, const uint32_t* a, const uint32_t* b) {
    if (DT == 0)
        asm volatile(
            "mma.sync.aligned.m16n8k16.row.col.f32.bf16.bf16.f32 "
            "{%0,%1,%2,%3}, {%4,%5,%6,%7}, {%8,%9}, {%0,%1,%2,%3};"
            : "+f"(d[0]), "+f"(d[1]), "+f"(d[2]), "+f"(d[3])
            : "r"(a[0]), "r"(a[1]), "r"(a[2]), "r"(a[3]), "r"(b[0]), "r"(b[1]));
    else
        asm volatile(
            "mma.sync.aligned.m16n8k16.row.col.f32.f16.f16.f32 "
            "{%0,%1,%2,%3}, {%4,%5,%6,%7}, {%8,%9}, {%0,%1,%2,%3};"
            : "+f"(d[0]), "+f"(d[1]), "+f"(d[2]), "+f"(d[3])
            : "r"(a[0]), "r"(a[1]), "r"(a[2]), "r"(a[3]), "r"(b[0]), "r"(b[1]));
}
__device__ __forceinline__ void bsplit(float v, __nv_bfloat16& h, __nv_bfloat16& l) {
    h = __float2bfloat16(v);
    l = __float2bfloat16(v - __bfloat162float(h));
}
__device__ __forceinline__ void hsplit(float v, __half& h, __half& l) {
    h = __float2half_rn(v);
    l = __float2half_rn(v - __half2float(h));
}

// ---- selectors ----------------------------------------------------------------
__device__ __forceinline__ void pickA(int s, long long off,
                                      const __nv_bfloat16*& h, const __nv_bfloat16*& l) {
    switch (s) {
        case 0: h = g_xh;  l = nullptr; break;
        case 1: h = g_ihh; l = nullptr; break;
        case 2: h = (const __nv_bfloat16*)g_h1h; l = (const __nv_bfloat16*)g_h1l; break;
        case 3: h = (const __nv_bfloat16*)g_f1h; l = (const __nv_bfloat16*)g_f1l; break;
        default: h = g_wth + off; l = g_wtl + off; return;
    }
}
__device__ __forceinline__ void pickB(int s, long long off,
                                      const __nv_bfloat16*& h) {
    switch (s) {
        case 0: h = g_wth + off; break;
        case 1: h = g_wM; break;
        default: h = g_wP; break;
    }
}
__device__ __forceinline__ __nv_bfloat16* pickCb(int s) {
    switch (s) { case 0: return g_y; case 1: return g_wM; default: return g_wP; }
}

// ---------------------------------------------------------------------------
// GEMM: C[M,Ntot] = A[M,K] @ B[Ntot,K]^T via mma.sync m16n8k16
//   CTA 128x128, 8 warps (2m x 4n), warp tile 64x32, K chunk 32, 3 stages.
//   PROD: 1 = Ah*Bh ; 2 = Ah*Bh + Al*Bh (activation-compensated)
//   EPI:  0 bf16 store | 2 f32+bias->g_f2 | 3 bias+relu->f1 fp16 planes | 4 att-dot
//   DT:   0 bf16, 1 fp16
// ---------------------------------------------------------------------------
#define PITCH 80

template <int PROD, int EPI, int DT>
__global__ __launch_bounds__(256, 2) void mma_gemm(
    int aSel, long long aOff, int lda, long long aZ,
    int bSel, long long bOff, long long bZ,
    int K, int cSel, long long cZ, int ldc,
    const float* __restrict__ bias)
{
    constexpr int PLANE  = 10240;
    constexpr int OFF_AL = PLANE;                          // PROD2 only
    constexpr int OFF_B  = (PROD == 1) ? PLANE : 2 * PLANE;
    constexpr int STAGE  = (PROD == 1) ? 2 * PLANE : 3 * PLANE;

    extern __shared__ char dsm[];
    const uint32_t sb = smem_u32(dsm);

    const int tid = threadIdx.x;
    const int lane = tid & 31;
    const int wid = tid >> 5;
    const int wm = wid & 1;
    const int wn = wid >> 1;

    const __nv_bfloat16 *Ah, *Al, *Bh;
    pickA(aSel, aOff + (long long)blockIdx.z * aZ, Ah, Al);
    pickB(bSel, bOff + (long long)blockIdx.z * bZ, Bh);

    const size_t mbase = (size_t)blockIdx.y * 128;
    const int nbase = blockIdx.x * 128;

    const int r0s = tid >> 2;
    const int seg = tid & 3;

    float acc[4][4][4];
#pragma unroll
    for (int i = 0; i < 4; i++)
#pragma unroll
        for (int j = 0; j < 4; j++)
#pragma unroll
            for (int q = 0; q < 4; q++) acc[i][j][q] = 0.f;

    const int nch = K >> 5;

    auto load_chunk = [&](int c, int stg) {
        const int kOff = c << 5;
        const uint32_t base = sb + stg * STAGE;
#pragma unroll
        for (int it = 0; it < 2; it++) {
            const int row = r0s + it * 64;
            const uint32_t d = base + row * PITCH + seg * 16;
            const size_t gA = (mbase + row) * (size_t)lda + kOff + seg * 8;
            const size_t gB = ((size_t)nbase + row) * (size_t)K + kOff + seg * 8;
            cp16(d, Ah + gA);
            cp16(d + OFF_B, Bh + gB);
            if (PROD == 2) cp16(d + OFF_AL, Al + gA);
        }
        cp_commit();
    };

    // 3-stage prologue
    load_chunk(0, 0);
    load_chunk(1, 1);

    int stg = 0, stg2 = 2;                 // stage of chunk c, and of chunk c+2
    for (int c = 0; c < nch; c++) {
        cp_wait<1>();                      // chunk c resident
        __syncthreads();                   // all warps done with stage (c-1)%3
        if (c + 2 < nch) load_chunk(c + 2, stg2);
        else             cp_commit();      // keep group accounting aligned

        const uint32_t sA = sb + stg * STAGE;
#pragma unroll
        for (int ks = 0; ks < 2; ks++) {
            const uint32_t colA = ks * 32 + ((lane >> 4) << 4);
            const uint32_t colB = ks * 32 + (((lane >> 3) & 1) << 4);

            uint32_t aH[4][4], bH[2][4];
            uint32_t aL[4][4];
#pragma unroll
            for (int mt = 0; mt < 4; mt++) {
                const uint32_t ad = sA + (wm * 64 + mt * 16 + (lane & 15)) * PITCH + colA;
                ldsm4(aH[mt][0], aH[mt][1], aH[mt][2], aH[mt][3], ad);
                if (PROD == 2)
                    ldsm4(aL[mt][0], aL[mt][1], aL[mt][2], aL[mt][3], ad + OFF_AL);
            }
#pragma unroll
            for (int nt2 = 0; nt2 < 2; nt2++) {
                const uint32_t bd = sA + OFF_B +
                    (wn * 32 + nt2 * 16 + (lane & 7) + ((lane >> 4) << 3)) * PITCH + colB;
                ldsm4(bH[nt2][0], bH[nt2][1], bH[nt2][2], bH[nt2][3], bd);
            }
#pragma unroll
            for (int mt = 0; mt < 4; mt++)
#pragma unroll
                for (int nt = 0; nt < 4; nt++) {
                    const uint32_t* bh = &bH[nt >> 1][(nt & 1) * 2];
                    mma16816<DT>(acc[mt][nt], aH[mt], bh);
                    if (PROD == 2) mma16816<DT>(acc[mt][nt], aL[mt], bh);
                }
        }
        stg = (stg == 2) ? 0 : stg + 1;
        stg2 = (stg2 == 2) ? 0 : stg2 + 1;
    }

    // ---- epilogues ----
    if (EPI == 4) {
        // att[n,h] += x[n,:] . t[n,:] over this tile's cols;  h = nbase>>9
        const int h = nbase >> 9;
#pragma unroll
        for (int mt = 0; mt < 4; mt++) {
            const size_t r = mbase + wm * 64 + mt * 16 + (lane >> 2);
            float p0 = 0.f, p1 = 0.f;
#pragma unroll
            for (int nt = 0; nt < 4; nt++) {
                const int col = nbase + wn * 32 + nt * 8 + ((lane & 3) << 1);
                const int i = col & 511;
                float2 x0 = __bfloat1622float2(*(const __nv_bfloat162*)(g_xh + r * 512 + i));
                float2 x1 = __bfloat1622float2(*(const __nv_bfloat162*)(g_xh + (r + 8) * 512 + i));
                p0 = fmaf(acc[mt][nt][0], x0.x, p0);
                p0 = fmaf(acc[mt][nt][1], x0.y, p0);
                p1 = fmaf(acc[mt][nt][2], x1.x, p1);
                p1 = fmaf(acc[mt][nt][3], x1.y, p1);
            }
            p0 += __shfl_xor_sync(0xffffffffu, p0, 1);
            p0 += __shfl_xor_sync(0xffffffffu, p0, 2);
            p1 += __shfl_xor_sync(0xffffffffu, p1, 1);
            p1 += __shfl_xor_sync(0xffffffffu, p1, 2);
            if ((lane & 3) == 0) {
                atomicAdd(&g_att[r * 4 + h], p0);
                atomicAdd(&g_att[(r + 8) * 4 + h], p1);
            }
        }
        return;
    }

    __nv_bfloat16* Cb = (EPI == 0) ? pickCb(cSel) + (size_t)blockIdx.z * cZ : nullptr;

#pragma unroll
    for (int mt = 0; mt < 4; mt++) {
        const size_t row = mbase + wm * 64 + mt * 16 + (lane >> 2);
#pragma unroll
        for (int nt = 0; nt < 4; nt++) {
            const int col = nbase + wn * 32 + nt * 8 + ((lane & 3) << 1);
            float v0 = acc[mt][nt][0], v1 = acc[mt][nt][1];
            float v2 = acc[mt][nt][2], v3 = acc[mt][nt][3];
            if (EPI >= 2) {
                const float bb0 = bias[col], bb1 = bias[col + 1];
                v0 += bb0; v1 += bb1; v2 += bb0; v3 += bb1;
            }
            if (EPI == 3) {
                v0 = fmaxf(v0, 0.f); v1 = fmaxf(v1, 0.f);
                v2 = fmaxf(v2, 0.f); v3 = fmaxf(v3, 0.f);
                __half h0, h1, l0, l1;
                __half2 ph, pl;
                size_t o = row * (size_t)ldc + col;
                hsplit(v0, h0, l0); hsplit(v1, h1, l1);
                ph.x = h0; ph.y = h1; pl.x = l0; pl.y = l1;
                *(__half2*)(g_f1h + o) = ph;
                *(__half2*)(g_f1l + o) = pl;
                o = (row + 8) * (size_t)ldc + col;
                hsplit(v2, h0, l0); hsplit(v3, h1, l1);
                ph.x = h0; ph.y = h1; pl.x = l0; pl.y = l1;
                *(__half2*)(g_f1h + o) = ph;
                *(__half2*)(g_f1l + o) = pl;
            } else if (EPI == 0) {
                __nv_bfloat162 p;
                p.x = __float2bfloat16(v0); p.y = __float2bfloat16(v1);
                *(__nv_bfloat162*)(Cb + row * (size_t)ldc + col) = p;
                p.x = __float2bfloat16(v2); p.y = __float2bfloat16(v3);
                *(__nv_bfloat162*)(Cb + (row + 8) * (size_t)ldc + col) = p;
            } else {  // EPI == 2
                float2 p;
                p.x = v0; p.y = v1;
                *(float2*)(g_f2 + row * (size_t)ldc + col) = p;
                p.x = v2; p.y = v3;
                *(float2*)(g_f2 + (row + 8) * (size_t)ldc + col) = p;
            }
        }
    }
}

// ---------------------------------------------------------------------------
// aux kernels
// ---------------------------------------------------------------------------
__global__ void split_in_kernel(const float* __restrict__ src, int dsel) {
    __nv_bfloat16* dh = dsel ? g_ihh : g_xh;
    const size_t i = (size_t)blockIdx.x * blockDim.x + threadIdx.x;
    const float4 v = ((const float4*)src)[i];
    __nv_bfloat162 a, b;
    a.x = __float2bfloat16(v.x); a.y = __float2bfloat16(v.y);
    b.x = __float2bfloat16(v.z); b.y = __float2bfloat16(v.w);
    *((__nv_bfloat162*)(dh + 4 * i)) = a;
    *((__nv_bfloat162*)(dh + 4 * i + 2)) = b;
}

__global__ void conv_w_kernel(const float* __restrict__ src, long long dstOff) {
    const size_t i = (size_t)blockIdx.x * blockDim.x + threadIdx.x;
    const float4 v = ((const float4*)src)[i];
    __nv_bfloat16* dh = g_wth + dstOff;
    __nv_bfloat162 a, b;
    a.x = __float2bfloat16(v.x); a.y = __float2bfloat16(v.y);
    b.x = __float2bfloat16(v.z); b.y = __float2bfloat16(v.w);
    *((__nv_bfloat162*)(dh + 4 * i)) = a;
    *((__nv_bfloat162*)(dh + 4 * i + 2)) = b;
}

// transpose: fp32 [K][Nn] -> 16-bit planes [Nn][K]; mode 0 = bf16 hi/lo, 1 = fp16 hi
__global__ void tsplit_kernel(const float* __restrict__ src, int K, int Nn,
                              long long srcZ, long long dstOff, long long dstZ,
                              int fp16mode) {
    __shared__ float t[32][33];
    const float* s = src + (size_t)blockIdx.z * srcZ;
    const size_t dbase = (size_t)dstOff + (size_t)blockIdx.z * dstZ;
    const int k0 = blockIdx.x * 32, n0 = blockIdx.y * 32;
    const int tx = threadIdx.x, ty = threadIdx.y;
    for (int r = ty; r < 32; r += 8)
        t[r][tx] = s[(size_t)(k0 + r) * Nn + n0 + tx];
    __syncthreads();
    for (int r = ty; r < 32; r += 8) {
        const float v = t[tx][r];
        const size_t o = dbase + (size_t)(n0 + r) * K + k0 + tx;
        if (fp16mode) {
            ((__half*)g_wth)[o] = __float2half_rn(v);
        } else {
            __nv_bfloat16 h, l;
            bsplit(v, h, l);
            g_wth[o] = h;
            g_wtl[o] = l;
        }
    }
}

__global__ void zero_att_kernel() {
    const size_t i = (size_t)blockIdx.x * blockDim.x + threadIdx.x;
    ((float4*)g_att)[i] = make_float4(0.f, 0.f, 0.f, 0.f);
    if (blockIdx.x == 0 && threadIdx.x < 4) g_denom[threadIdx.x] = 0.f;
}

__global__ void denom_kernel() {
    const int idx = blockIdx.x * blockDim.x + threadIdx.x;
    const float4 v = *(const float4*)(g_att + (size_t)idx * 4);
    float e0 = expf(v.x * ATT_SCALE), e1 = expf(v.y * ATT_SCALE);
    float e2 = expf(v.z * ATT_SCALE), e3 = expf(v.w * ATT_SCALE);
#pragma unroll
    for (int o = 16; o; o >>= 1) {
        e0 += __shfl_down_sync(0xffffffffu, e0, o);
        e1 += __shfl_down_sync(0xffffffffu, e1, o);
        e2 += __shfl_down_sync(0xffffffffu, e2, o);
        e3 += __shfl_down_sync(0xffffffffu, e3, o);
    }
    __shared__ float sm[4][8];
    const int w = threadIdx.x >> 5, lane = threadIdx.x & 31;
    if (lane == 0) { sm[0][w] = e0; sm[1][w] = e1; sm[2][w] = e2; sm[3][w] = e3; }
    __syncthreads();
    if (threadIdx.x < 4) {
        float s = 0.f;
#pragma unroll
        for (int i = 0; i < 8; i++) s += sm[threadIdx.x][i];
        atomicAdd(&g_denom[threadIdx.x], s);
    }
}

// h1 = LN( sum_h alpha[n,h]*y[n,h*512+o] + x[n,o] ); writes fp16 hi/lo planes
__global__ void ln1_fused(const float* __restrict__ x,
                          const float* __restrict__ gam,
                          const float* __restrict__ bet) {
    const int n = blockIdx.x;
    const int t = threadIdx.x;
    const size_t xb = (size_t)n * 512;
    const size_t yb = (size_t)n * 2048;

    float alpha[4];
#pragma unroll
    for (int h = 0; h < 4; h++)
        alpha[h] = expf(g_att[n * 4 + h] * ATT_SCALE) / g_denom[h];

    float mo0 = 0.f, mo1 = 0.f;
#pragma unroll
    for (int h = 0; h < 4; h++) {
        mo0 = fmaf(alpha[h], __bfloat162float(g_y[yb + h * 512 + t]), mo0);
        mo1 = fmaf(alpha[h], __bfloat162float(g_y[yb + h * 512 + t + 256]), mo1);
    }
    const float v0 = mo0 + x[xb + t];
    const float v1 = mo1 + x[xb + t + 256];

    float s = v0 + v1, q = v0 * v0 + v1 * v1;
#pragma unroll
    for (int o = 16; o; o >>= 1) {
        s += __shfl_down_sync(0xffffffffu, s, o);
        q += __shfl_down_sync(0xffffffffu, q, o);
    }
    __shared__ float ss[8], qq[8];
    __shared__ float s_mean, s_rstd;
    const int w = t >> 5, lane = t & 31;
    if (lane == 0) { ss[w] = s; qq[w] = q; }
    __syncthreads();
    if (t == 0) {
        float S = 0.f, Q2 = 0.f;
#pragma unroll
        for (int i = 0; i < 8; i++) { S += ss[i]; Q2 += qq[i]; }
        const float mean = S * (1.0f / 512.0f);
        s_mean = mean;
        s_rstd = rsqrtf(Q2 * (1.0f / 512.0f) - mean * mean + 1e-5f);
    }
    __syncthreads();
    const float mean = s_mean, r = s_rstd;
    const float o0 = (v0 - mean) * r * gam[t] + bet[t];
    const float o1 = (v1 - mean) * r * gam[t + 256] + bet[t + 256];
    __half h, l;
    hsplit(o0, h, l); g_h1h[xb + t] = h;       g_h1l[xb + t] = l;
    hsplit(o1, h, l); g_h1h[xb + t + 256] = h; g_h1l[xb + t + 256] = l;
}

// out = LN(f2 + h1), h1 reconstructed from fp16 hi+lo planes
__global__ void ln2_kernel(const float* __restrict__ gam,
                           const float* __restrict__ bet,
                           float* __restrict__ out) {
    const int n = blockIdx.x;
    const int t = threadIdx.x;
    const size_t base = (size_t)n * 512;
    const float h10 = __half2float(g_h1h[base + t]) + __half2float(g_h1l[base + t]);
    const float h11 = __half2float(g_h1h[base + t + 256]) + __half2float(g_h1l[base + t + 256]);
    const float v0 = g_f2[base + t] + h10;
    const float v1 = g_f2[base + t + 256] + h11;
    float s = v0 + v1, q = v0 * v0 + v1 * v1;
#pragma unroll
    for (int o = 16; o; o >>= 1) {
        s += __shfl_down_sync(0xffffffffu, s, o);
        q += __shfl_down_sync(0xffffffffu, q, o);
    }
    __shared__ float ss[8], qq[8];
    __shared__ float s_mean, s_rstd;
    const int w = t >> 5, lane = t & 31;
    if (lane == 0) { ss[w] = s; qq[w] = q; }
    __syncthreads();
    if (t == 0) {
        float S = 0.f, Q2 = 0.f;
#pragma unroll
        for (int i = 0; i < 8; i++) { S += ss[i]; Q2 += qq[i]; }
        const float mean = S * (1.0f / 512.0f);
        s_mean = mean;
        s_rstd = rsqrtf(Q2 * (1.0f / 512.0f) - mean * mean + 1e-5f);
    }
    __syncthreads();
    const float mean = s_mean, r = s_rstd;
    out[base + t]       = (v0 - mean) * r * gam[t]       + bet[t];
    out[base + t + 256] = (v1 - mean) * r * gam[t + 256] + bet[t + 256];
}

// ---------------------------------------------------------------------------
#define SMEM_P1 61440    // 3 stages x 2 planes
#define SMEM_P2 92160    // 3 stages x 3 planes

extern "C" void kernel_launch(void* const* d_in, const int* in_sizes, int n_in,
                              void* d_out, int out_size) {
    (void)in_sizes; (void)n_in; (void)out_size;
    const float* x   = (const float*)d_in[0];
    const float* ih  = (const float*)d_in[1];
    const float* Wq  = (const float*)d_in[4];
    const float* Wk  = (const float*)d_in[5];
    const float* Wv  = (const float*)d_in[6];
    const float* Wc  = (const float*)d_in[7];
    const float* W1  = (const float*)d_in[8];
    const float* b1  = (const float*)d_in[9];
    const float* W2  = (const float*)d_in[10];
    const float* b2  = (const float*)d_in[11];
    const float* lng = (const float*)d_in[12];
    const float* lnb = (const float*)d_in[13];
    float* out = (float*)d_out;

    cudaFuncSetAttribute(mma_gemm<1, 0, 0>, cudaFuncAttributeMaxDynamicSharedMemorySize, SMEM_P1);
    cudaFuncSetAttribute(mma_gemm<1, 4, 0>, cudaFuncAttributeMaxDynamicSharedMemorySize, SMEM_P1);
    cudaFuncSetAttribute(mma_gemm<2, 3, 1>, cudaFuncAttributeMaxDynamicSharedMemorySize, SMEM_P2);
    cudaFuncSetAttribute(mma_gemm<2, 2, 1>, cudaFuncAttributeMaxDynamicSharedMemorySize, SMEM_P2);

    const dim3 tb(32, 8);

    // weight prep
    tsplit_kernel<<<dim3(16, 16, 4), tb>>>(Wq, 512, 512, 262144, WOFF_Q, 262144, 0);
    tsplit_kernel<<<dim3(16, 16, 4), tb>>>(Wk, 512, 512, 262144, WOFF_K, 262144, 0);
    conv_w_kernel<<<1024, 256>>>(Wv, WOFF_V);
    tsplit_kernel<<<dim3(64, 16, 1), tb>>>(Wc, 2048, 512, 0, WOFF_C, 0, 0);
    tsplit_kernel<<<dim3(16, 32, 1), tb>>>(W1, 512, 1024, 0, WOFF_1, 0, 1);
    tsplit_kernel<<<dim3(32, 16, 1), tb>>>(W2, 1024, 512, 0, WOFF_2, 0, 1);

    split_in_kernel<<<16384, 256>>>(x, 0);
    split_in_kernel<<<16384, 256>>>(ih, 1);
    zero_att_kernel<<<128, 256>>>();

    // M_h = Wq_h^T @ Wk_h  -> g_wM
    mma_gemm<1, 0, 0><<<dim3(4, 4, 4), 256, SMEM_P1>>>(
        4, WOFF_Q, 512, 262144, 0, WOFF_K, 262144, 512, 1, 262144, 512, nullptr);
    // P^T_h = Wc_h^T @ Wv_h^T -> g_wP
    mma_gemm<1, 0, 0><<<dim3(4, 4, 4), 256, SMEM_P1>>>(
        4, WOFF_C, 2048, 512, 0, WOFF_V, 262144, 512, 2, 262144, 512, nullptr);

    // t = ih @ M^T with fused att-dot epilogue
    mma_gemm<1, 4, 0><<<dim3(16, 256), 256, SMEM_P1>>>(
        1, 0, 512, 0, 1, 0, 0, 512, 0, 0, 0, nullptr);
    denom_kernel<<<128, 256>>>();

    // y = x @ P -> g_y bf16 [N,2048]
    mma_gemm<1, 0, 0><<<dim3(16, 256), 256, SMEM_P1>>>(
        0, 0, 512, 0, 2, 0, 0, 512, 0, 0, 2048, nullptr);

    // h1 = LN(sum_h alpha*y + x) -> fp16 planes
    ln1_fused<<<NN, 256>>>(x, lng, lnb);

    // f1 = relu(h1 @ W1 + b1) -> fp16 planes   (2-product fp16)
    mma_gemm<2, 3, 1><<<dim3(8, 256), 256, SMEM_P2>>>(
        2, 0, 512, 0, 0, WOFF_1, 0, 512, 0, 0, 1024, b1);
    // f2 = f1 @ W2 + b2 -> f32
    mma_gemm<2, 2, 1><<<dim3(4, 256), 256, SMEM_P2>>>(
        3, 0, 1024, 0, 0, WOFF_2, 0, 1024, 0, 0, 512, b2);

    ln2_kernel<<<NN, 256>>>(lng, lnb, out);
}

// round 11
// speedup vs baseline: 1.0703x; 1.0647x over previous
#include <cuda_runtime.h>
#include <cuda_bf16.h>
#include <cuda_fp16.h>
#include <cstdint>

// ---------------------------------------------------------------------------
// TransformerBlock N=32768, IN=512, HID=512, HEAD=4  (mma.sync path)
//   M_h  = Wq_h^T @ Wk_h ;  P^T_h = Wc_h^T @ Wv_h^T      (tiny precompute)
//   att[n,h] = x_n . (ih @ M_h^T)_n                      (fused epilogue)
//   alpha = softmax over nodes; y = x @ P
//   h1 = LN( sum_h alpha[n,h]*y_h[n] + x )               (fused)
//   out = LN( relu(h1@W1+b1)@W2+b2 + h1 )
// Attention branch: single-product bf16. FFN: 2-product fp16.
// GEMM: 4 warps, warp tile 64x64 (kills 3x LDSM redundancy of 2x4 layout).
// ---------------------------------------------------------------------------
#define NN 32768
#define ATT_SCALE 0.044194173824159216f

// ---- scratch ----------------------------------------------------------------
__device__ __nv_bfloat16 g_xh[(size_t)NN * 512];
__device__ __nv_bfloat16 g_ihh[(size_t)NN * 512];
__device__ __nv_bfloat16 g_wth[5242880], g_wtl[5242880];  // weight planes (16-bit slots)
__device__ __nv_bfloat16 g_wM[2048 * 512];                // M:  [h*512+i][j]
__device__ __nv_bfloat16 g_wP[2048 * 512];                // P^T:[h*512+o][d]
__device__ __nv_bfloat16 g_y[(size_t)NN * 2048];          // x @ P  (head-major)
__device__ float g_f2[(size_t)NN * 512];
__device__ __half g_h1h[(size_t)NN * 512],  g_h1l[(size_t)NN * 512];
__device__ __half g_f1h[(size_t)NN * 1024], g_f1l[(size_t)NN * 1024];
__device__ float g_att[NN * 4];
__device__ float g_denom[4];

#define WOFF_Q  0           // Wq^T  [4][512 i][512 d]   bf16
#define WOFF_K  1048576     // Wk^T  [4][512 j][512 d]   bf16
#define WOFF_V  2097152     // Wv (plain) [4][512 d][512 c] bf16
#define WOFF_C  3145728     // Wc^T  [512 o][2048 c]     bf16
#define WOFF_1  4194304     // W1^T  [1024][512]         fp16
#define WOFF_2  4718592     // W2^T  [512][1024]         fp16

// ---- PTX helpers ------------------------------------------------------------
__device__ __forceinline__ uint32_t smem_u32(const void* p) {
    uint32_t a;
    asm("{ .reg .u64 t; cvta.to.shared.u64 t, %1; cvt.u32.u64 %0, t; }" : "=r"(a) : "l"(p));
    return a;
}
__device__ __forceinline__ void cp16(uint32_t dst, const void* src) {
    asm volatile("cp.async.ca.shared.global [%0], [%1], 16;" :: "r"(dst), "l"(src));
}
__device__ __forceinline__ void cp_commit() {
    asm volatile("cp.async.commit_group;" ::: "memory");
}
template <int N>
__device__ __forceinline__ void cp_wait() {
    asm volatile("cp.async.wait_group %0;" :: "n"(N) : "memory");
}
__device__ __forceinline__ void ldsm4(uint32_t& r0, uint32_t& r1, uint32_t& r2, uint32_t& r3,
                                      uint32_t addr) {
    asm volatile("ldmatrix.sync.aligned.m8n8.x4.shared.b16 {%0,%1,%2,%3}, [%4];"
                 : "=r"(r0), "=r"(r1), "=r"(r2), "=r"(r3) : "r"(addr));
}
template <int DT>  // 0 = bf16, 1 = fp16
__device__ __forceinline__ void mma16816(float* d, const uint32_t* a, const uint32_t* b) {
    if (DT == 0)
        asm volatile(
            "mma.sync.aligned.m16n8k16.row.col.f32.bf16.bf16.f32 "
            "{%0,%1,%2,%3}, {%4,%5,%6,%7}, {%8,%9}, {%0,%1,%2,%3};"
            : "+f"(d[0]), "+f"(d[1]), "+f"(d[2]), "+f"(d[3])
            : "r"(a[0]), "r"(a[1]), "r"(a[2]), "r"(a[3]), "r"(b[0]), "r"(b[1]));
    else
        asm volatile(
            "mma.sync.aligned.m16n8k16.row.col.f32.f16.f16.f32 "
            "{%0,%1,%2,%3}, {%4,%5,%6,%7}, {%8,%9}, {%0,%1,%2,%3};"
            : "+f"(d[0]), "+f"(d[1]), "+f"(d[2]), "+f"(d[3])
            : "r"(a[0]), "r"(a[1]), "r"(a[2]), "r"(a[3]), "r"(b[0]), "r"(b[1]));
}
__device__ __forceinline__ void bsplit(float v, __nv_bfloat16& h, __nv_bfloat16& l) {
    h = __float2bfloat16(v);
    l = __float2bfloat16(v - __bfloat162float(h));
}
__device__ __forceinline__ void hsplit(float v, __half& h, __half& l) {
    h = __float2half_rn(v);
    l = __float2half_rn(v - __half2float(h));
}

// ---- selectors ----------------------------------------------------------------
__device__ __forceinline__ void pickA(int s, long long off,
                                      const __nv_bfloat16*& h, const __nv_bfloat16*& l) {
    switch (s) {
        case 0: h = g_xh;  l = nullptr; break;
        case 1: h = g_ihh; l = nullptr; break;
        case 2: h = (const __nv_bfloat16*)g_h1h; l = (const __nv_bfloat16*)g_h1l; break;
        case 3: h = (const __nv_bfloat16*)g_f1h; l = (const __nv_bfloat16*)g_f1l; break;
        default: h = g_wth + off; l = g_wtl + off; return;
    }
}
__device__ __forceinline__ void pickB(int s, long long off,
                                      const __nv_bfloat16*& h) {
    switch (s) {
        case 0: h = g_wth + off; break;
        case 1: h = g_wM; break;
        default: h = g_wP; break;
    }
}
__device__ __forceinline__ __nv_bfloat16* pickCb(int s) {
    switch (s) { case 0: return g_y; case 1: return g_wM; default: return g_wP; }
}

// ---------------------------------------------------------------------------
// GEMM: C[M,Ntot] = A[M,K] @ B[Ntot,K]^T via mma.sync m16n8k16
//   CTA 128x128, 4 warps (2m x 2n), warp tile 64x64, K chunk 32, 3 stages.
//   PROD: 1 = Ah*Bh ; 2 = Ah*Bh + Al*Bh (activation-compensated)
//   EPI:  0 bf16 store | 2 f32+bias->g_f2 | 3 bias+relu->f1 fp16 planes | 4 att-dot
//   DT:   0 bf16, 1 fp16
// ---------------------------------------------------------------------------
#define PITCH 80

template <int PROD, int EPI, int DT>
__global__ __launch_bounds__(128, 2) void mma_gemm(
    int aSel, long long aOff, int lda, long long aZ,
    int bSel, long long bOff, long long bZ,
    int K, int cSel, long long cZ, int ldc,
    const float* __restrict__ bias)
{
    constexpr int PLANE  = 10240;
    constexpr int OFF_AL = PLANE;                          // PROD2 only
    constexpr int OFF_B  = (PROD == 1) ? PLANE : 2 * PLANE;
    constexpr int STAGE  = (PROD == 1) ? 2 * PLANE : 3 * PLANE;

    extern __shared__ char dsm[];
    const uint32_t sb = smem_u32(dsm);

    const int tid = threadIdx.x;
    const int lane = tid & 31;
    const int wid = tid >> 5;
    const int wm = wid & 1;          // 0..1  (64-row halves)
    const int wn = wid >> 1;         // 0..1  (64-col halves)

    const __nv_bfloat16 *Ah, *Al, *Bh;
    pickA(aSel, aOff + (long long)blockIdx.z * aZ, Ah, Al);
    pickB(bSel, bOff + (long long)blockIdx.z * bZ, Bh);

    const size_t mbase = (size_t)blockIdx.y * 128;
    const int nbase = blockIdx.x * 128;

    const int seg = tid & 3;
    const int row0 = tid >> 2;       // 0..31; rows row0 + 32*it

    float acc[4][8][4];
#pragma unroll
    for (int i = 0; i < 4; i++)
#pragma unroll
        for (int j = 0; j < 8; j++)
#pragma unroll
            for (int q = 0; q < 4; q++) acc[i][j][q] = 0.f;

    const int nch = K >> 5;

    auto load_chunk = [&](int c, int stg) {
        const int kOff = c << 5;
        const uint32_t base = sb + stg * STAGE;
#pragma unroll
        for (int it = 0; it < 4; it++) {
            const int row = row0 + it * 32;
            const uint32_t d = base + row * PITCH + seg * 16;
            const size_t gA = (mbase + row) * (size_t)lda + kOff + seg * 8;
            const size_t gB = ((size_t)nbase + row) * (size_t)K + kOff + seg * 8;
            cp16(d, Ah + gA);
            cp16(d + OFF_B, Bh + gB);
            if (PROD == 2) cp16(d + OFF_AL, Al + gA);
        }
        cp_commit();
    };

    // 3-stage prologue
    load_chunk(0, 0);
    load_chunk(1, 1);

    int stg = 0, stg2 = 2;
    for (int c = 0; c < nch; c++) {
        cp_wait<1>();
        __syncthreads();
        if (c + 2 < nch) load_chunk(c + 2, stg2);
        else             cp_commit();

        const uint32_t sA = sb + stg * STAGE;
#pragma unroll
        for (int ks = 0; ks < 2; ks++) {
            const uint32_t colA = ks * 32 + ((lane >> 4) << 4);
            const uint32_t colB = ks * 32 + (((lane >> 3) & 1) << 4);

            uint32_t aH[4][4], bH[4][4];
            uint32_t aL[4][4];
#pragma unroll
            for (int mt = 0; mt < 4; mt++) {
                const uint32_t ad = sA + (wm * 64 + mt * 16 + (lane & 15)) * PITCH + colA;
                ldsm4(aH[mt][0], aH[mt][1], aH[mt][2], aH[mt][3], ad);
                if (PROD == 2)
                    ldsm4(aL[mt][0], aL[mt][1], aL[mt][2], aL[mt][3], ad + OFF_AL);
            }
#pragma unroll
            for (int nt2 = 0; nt2 < 4; nt2++) {
                const uint32_t bd = sA + OFF_B +
                    (wn * 64 + nt2 * 16 + (lane & 7) + ((lane >> 4) << 3)) * PITCH + colB;
                ldsm4(bH[nt2][0], bH[nt2][1], bH[nt2][2], bH[nt2][3], bd);
            }
#pragma unroll
            for (int mt = 0; mt < 4; mt++)
#pragma unroll
                for (int nt = 0; nt < 8; nt++) {
                    const uint32_t* bh = &bH[nt >> 1][(nt & 1) * 2];
                    mma16816<DT>(acc[mt][nt], aH[mt], bh);
                    if (PROD == 2) mma16816<DT>(acc[mt][nt], aL[mt], bh);
                }
        }
        stg = (stg == 2) ? 0 : stg + 1;
        stg2 = (stg2 == 2) ? 0 : stg2 + 1;
    }

    // ---- epilogues ----
    if (EPI == 4) {
        // att[n,h] += x[n,:] . t[n,:] over this tile's cols;  h = nbase>>9
        const int h = nbase >> 9;
#pragma unroll
        for (int mt = 0; mt < 4; mt++) {
            const size_t r = mbase + wm * 64 + mt * 16 + (lane >> 2);
            float p0 = 0.f, p1 = 0.f;
#pragma unroll
            for (int nt = 0; nt < 8; nt++) {
                const int col = nbase + wn * 64 + nt * 8 + ((lane & 3) << 1);
                const int i = col & 511;
                float2 x0 = __bfloat1622float2(*(const __nv_bfloat162*)(g_xh + r * 512 + i));
                float2 x1 = __bfloat1622float2(*(const __nv_bfloat162*)(g_xh + (r + 8) * 512 + i));
                p0 = fmaf(acc[mt][nt][0], x0.x, p0);
                p0 = fmaf(acc[mt][nt][1], x0.y, p0);
                p1 = fmaf(acc[mt][nt][2], x1.x, p1);
                p1 = fmaf(acc[mt][nt][3], x1.y, p1);
            }
            p0 += __shfl_xor_sync(0xffffffffu, p0, 1);
            p0 += __shfl_xor_sync(0xffffffffu, p0, 2);
            p1 += __shfl_xor_sync(0xffffffffu, p1, 1);
            p1 += __shfl_xor_sync(0xffffffffu, p1, 2);
            if ((lane & 3) == 0) {
                atomicAdd(&g_att[r * 4 + h], p0);
                atomicAdd(&g_att[(r + 8) * 4 + h], p1);
            }
        }
        return;
    }

    __nv_bfloat16* Cb = (EPI == 0) ? pickCb(cSel) + (size_t)blockIdx.z * cZ : nullptr;

#pragma unroll
    for (int mt = 0; mt < 4; mt++) {
        const size_t row = mbase + wm * 64 + mt * 16 + (lane >> 2);
#pragma unroll
        for (int nt = 0; nt < 8; nt++) {
            const int col = nbase + wn * 64 + nt * 8 + ((lane & 3) << 1);
            float v0 = acc[mt][nt][0], v1 = acc[mt][nt][1];
            float v2 = acc[mt][nt][2], v3 = acc[mt][nt][3];
            if (EPI >= 2) {
                const float bb0 = bias[col], bb1 = bias[col + 1];
                v0 += bb0; v1 += bb1; v2 += bb0; v3 += bb1;
            }
            if (EPI == 3) {
                v0 = fmaxf(v0, 0.f); v1 = fmaxf(v1, 0.f);
                v2 = fmaxf(v2, 0.f); v3 = fmaxf(v3, 0.f);
                __half h0, h1, l0, l1;
                __half2 ph, pl;
                size_t o = row * (size_t)ldc + col;
                hsplit(v0, h0, l0); hsplit(v1, h1, l1);
                ph.x = h0; ph.y = h1; pl.x = l0; pl.y = l1;
                *(__half2*)(g_f1h + o) = ph;
                *(__half2*)(g_f1l + o) = pl;
                o = (row + 8) * (size_t)ldc + col;
                hsplit(v2, h0, l0); hsplit(v3, h1, l1);
                ph.x = h0; ph.y = h1; pl.x = l0; pl.y = l1;
                *(__half2*)(g_f1h + o) = ph;
                *(__half2*)(g_f1l + o) = pl;
            } else if (EPI == 0) {
                __nv_bfloat162 p;
                p.x = __float2bfloat16(v0); p.y = __float2bfloat16(v1);
                *(__nv_bfloat162*)(Cb + row * (size_t)ldc + col) = p;
                p.x = __float2bfloat16(v2); p.y = __float2bfloat16(v3);
                *(__nv_bfloat162*)(Cb + (row + 8) * (size_t)ldc + col) = p;
            } else {  // EPI == 2
                float2 p;
                p.x = v0; p.y = v1;
                *(float2*)(g_f2 + row * (size_t)ldc + col) = p;
                p.x = v2; p.y = v3;
                *(float2*)(g_f2 + (row + 8) * (size_t)ldc + col) = p;
            }
        }
    }
}

// ---------------------------------------------------------------------------
// aux kernels
// ---------------------------------------------------------------------------
__global__ void split_in_kernel(const float* __restrict__ src, int dsel) {
    __nv_bfloat16* dh = dsel ? g_ihh : g_xh;
    const size_t i = (size_t)blockIdx.x * blockDim.x + threadIdx.x;
    const float4 v = ((const float4*)src)[i];
    __nv_bfloat162 a, b;
    a.x = __float2bfloat16(v.x); a.y = __float2bfloat16(v.y);
    b.x = __float2bfloat16(v.z); b.y = __float2bfloat16(v.w);
    *((__nv_bfloat162*)(dh + 4 * i)) = a;
    *((__nv_bfloat162*)(dh + 4 * i + 2)) = b;
}

__global__ void conv_w_kernel(const float* __restrict__ src, long long dstOff) {
    const size_t i = (size_t)blockIdx.x * blockDim.x + threadIdx.x;
    const float4 v = ((const float4*)src)[i];
    __nv_bfloat16* dh = g_wth + dstOff;
    __nv_bfloat162 a, b;
    a.x = __float2bfloat16(v.x); a.y = __float2bfloat16(v.y);
    b.x = __float2bfloat16(v.z); b.y = __float2bfloat16(v.w);
    *((__nv_bfloat162*)(dh + 4 * i)) = a;
    *((__nv_bfloat162*)(dh + 4 * i + 2)) = b;
}

// transpose: fp32 [K][Nn] -> 16-bit planes [Nn][K]; mode 0 = bf16 hi/lo, 1 = fp16 hi
__global__ void tsplit_kernel(const float* __restrict__ src, int K, int Nn,
                              long long srcZ, long long dstOff, long long dstZ,
                              int fp16mode) {
    __shared__ float t[32][33];
    const float* s = src + (size_t)blockIdx.z * srcZ;
    const size_t dbase = (size_t)dstOff + (size_t)blockIdx.z * dstZ;
    const int k0 = blockIdx.x * 32, n0 = blockIdx.y * 32;
    const int tx = threadIdx.x, ty = threadIdx.y;
    for (int r = ty; r < 32; r += 8)
        t[r][tx] = s[(size_t)(k0 + r) * Nn + n0 + tx];
    __syncthreads();
    for (int r = ty; r < 32; r += 8) {
        const float v = t[tx][r];
        const size_t o = dbase + (size_t)(n0 + r) * K + k0 + tx;
        if (fp16mode) {
            ((__half*)g_wth)[o] = __float2half_rn(v);
        } else {
            __nv_bfloat16 h, l;
            bsplit(v, h, l);
            g_wth[o] = h;
            g_wtl[o] = l;
        }
    }
}

__global__ void zero_att_kernel() {
    const size_t i = (size_t)blockIdx.x * blockDim.x + threadIdx.x;
    ((float4*)g_att)[i] = make_float4(0.f, 0.f, 0.f, 0.f);
    if (blockIdx.x == 0 && threadIdx.x < 4) g_denom[threadIdx.x] = 0.f;
}

__global__ void denom_kernel() {
    const int idx = blockIdx.x * blockDim.x + threadIdx.x;
    const float4 v = *(const float4*)(g_att + (size_t)idx * 4);
    float e0 = expf(v.x * ATT_SCALE), e1 = expf(v.y * ATT_SCALE);
    float e2 = expf(v.z * ATT_SCALE), e3 = expf(v.w * ATT_SCALE);
#pragma unroll
    for (int o = 16; o; o >>= 1) {
        e0 += __shfl_down_sync(0xffffffffu, e0, o);
        e1 += __shfl_down_sync(0xffffffffu, e1, o);
        e2 += __shfl_down_sync(0xffffffffu, e2, o);
        e3 += __shfl_down_sync(0xffffffffu, e3, o);
    }
    __shared__ float sm[4][8];
    const int w = threadIdx.x >> 5, lane = threadIdx.x & 31;
    if (lane == 0) { sm[0][w] = e0; sm[1][w] = e1; sm[2][w] = e2; sm[3][w] = e3; }
    __syncthreads();
    if (threadIdx.x < 4) {
        float s = 0.f;
#pragma unroll
        for (int i = 0; i < 8; i++) s += sm[threadIdx.x][i];
        atomicAdd(&g_denom[threadIdx.x], s);
    }
}

// h1 = LN( sum_h alpha[n,h]*y[n,h*512+c] + x[n,c] ); thread t owns cols 2t, 2t+1
__global__ void ln1_fused(const float* __restrict__ x,
                          const float* __restrict__ gam,
                          const float* __restrict__ bet) {
    const int n = blockIdx.x;
    const int t = threadIdx.x;
    const size_t xb = (size_t)n * 512;
    const size_t yb = (size_t)n * 2048;
    const int c = t * 2;

    float alpha[4];
#pragma unroll
    for (int h = 0; h < 4; h++)
        alpha[h] = expf(g_att[n * 4 + h] * ATT_SCALE) / g_denom[h];

    float mo0 = 0.f, mo1 = 0.f;
#pragma unroll
    for (int h = 0; h < 4; h++) {
        float2 yv = __bfloat1622float2(*(const __nv_bfloat162*)(g_y + yb + h * 512 + c));
        mo0 = fmaf(alpha[h], yv.x, mo0);
        mo1 = fmaf(alpha[h], yv.y, mo1);
    }
    const float2 xv = *(const float2*)(x + xb + c);
    const float v0 = mo0 + xv.x;
    const float v1 = mo1 + xv.y;

    float s = v0 + v1, q = v0 * v0 + v1 * v1;
#pragma unroll
    for (int o = 16; o; o >>= 1) {
        s += __shfl_down_sync(0xffffffffu, s, o);
        q += __shfl_down_sync(0xffffffffu, q, o);
    }
    __shared__ float ss[8], qq[8];
    __shared__ float s_mean, s_rstd;
    const int w = t >> 5, lane = t & 31;
    if (lane == 0) { ss[w] = s; qq[w] = q; }
    __syncthreads();
    if (t == 0) {
        float S = 0.f, Q2 = 0.f;
#pragma unroll
        for (int i = 0; i < 8; i++) { S += ss[i]; Q2 += qq[i]; }
        const float mean = S * (1.0f / 512.0f);
        s_mean = mean;
        s_rstd = rsqrtf(Q2 * (1.0f / 512.0f) - mean * mean + 1e-5f);
    }
    __syncthreads();
    const float mean = s_mean, r = s_rstd;
    const float2 gv = *(const float2*)(gam + c);
    const float2 bv = *(const float2*)(bet + c);
    const float o0 = (v0 - mean) * r * gv.x + bv.x;
    const float o1 = (v1 - mean) * r * gv.y + bv.y;
    __half h0, l0, h1, l1;
    hsplit(o0, h0, l0); hsplit(o1, h1, l1);
    __half2 ph, pl;
    ph.x = h0; ph.y = h1; pl.x = l0; pl.y = l1;
    *(__half2*)(g_h1h + xb + c) = ph;
    *(__half2*)(g_h1l + xb + c) = pl;
}

// out = LN(f2 + h1), h1 reconstructed from fp16 hi+lo planes
__global__ void ln2_kernel(const float* __restrict__ gam,
                           const float* __restrict__ bet,
                           float* __restrict__ out) {
    const int n = blockIdx.x;
    const int t = threadIdx.x;
    const size_t base = (size_t)n * 512;
    const int c = t * 2;
    const __half2 hh = *(const __half2*)(g_h1h + base + c);
    const __half2 hl = *(const __half2*)(g_h1l + base + c);
    const float2 fv = *(const float2*)(g_f2 + base + c);
    const float v0 = fv.x + __half2float(hh.x) + __half2float(hl.x);
    const float v1 = fv.y + __half2float(hh.y) + __half2float(hl.y);
    float s = v0 + v1, q = v0 * v0 + v1 * v1;
#pragma unroll
    for (int o = 16; o; o >>= 1) {
        s += __shfl_down_sync(0xffffffffu, s, o);
        q += __shfl_down_sync(0xffffffffu, q, o);
    }
    __shared__ float ss[8], qq[8];
    __shared__ float s_mean, s_rstd;
    const int w = t >> 5, lane = t & 31;
    if (lane == 0) { ss[w] = s; qq[w] = q; }
    __syncthreads();
    if (t == 0) {
        float S = 0.f, Q2 = 0.f;
#pragma unroll
        for (int i = 0; i < 8; i++) { S += ss[i]; Q2 += qq[i]; }
        const float mean = S * (1.0f / 512.0f);
        s_mean = mean;
        s_rstd = rsqrtf(Q2 * (1.0f / 512.0f) - mean * mean + 1e-5f);
    }
    __syncthreads();
    const float mean = s_mean, r = s_rstd;
    const float2 gv = *(const float2*)(gam + c);
    const float2 bv = *(const float2*)(bet + c);
    float2 o;
    o.x = (v0 - mean) * r * gv.x + bv.x;
    o.y = (v1 - mean) * r * gv.y + bv.y;
    *(float2*)(out + base + c) = o;
}

// ---------------------------------------------------------------------------
#define SMEM_P1 61440    // 3 stages x 2 planes
#define SMEM_P2 92160    // 3 stages x 3 planes

extern "C" void kernel_launch(void* const* d_in, const int* in_sizes, int n_in,
                              void* d_out, int out_size) {
    (void)in_sizes; (void)n_in; (void)out_size;
    const float* x   = (const float*)d_in[0];
    const float* ih  = (const float*)d_in[1];
    const float* Wq  = (const float*)d_in[4];
    const float* Wk  = (const float*)d_in[5];
    const float* Wv  = (const float*)d_in[6];
    const float* Wc  = (const float*)d_in[7];
    const float* W1  = (const float*)d_in[8];
    const float* b1  = (const float*)d_in[9];
    const float* W2  = (const float*)d_in[10];
    const float* b2  = (const float*)d_in[11];
    const float* lng = (const float*)d_in[12];
    const float* lnb = (const float*)d_in[13];
    float* out = (float*)d_out;

    cudaFuncSetAttribute(mma_gemm<1, 0, 0>, cudaFuncAttributeMaxDynamicSharedMemorySize, SMEM_P1);
    cudaFuncSetAttribute(mma_gemm<1, 4, 0>, cudaFuncAttributeMaxDynamicSharedMemorySize, SMEM_P1);
    cudaFuncSetAttribute(mma_gemm<2, 3, 1>, cudaFuncAttributeMaxDynamicSharedMemorySize, SMEM_P2);
    cudaFuncSetAttribute(mma_gemm<2, 2, 1>, cudaFuncAttributeMaxDynamicSharedMemorySize, SMEM_P2);

    const dim3 tb(32, 8);

    // weight prep
    tsplit_kernel<<<dim3(16, 16, 4), tb>>>(Wq, 512, 512, 262144, WOFF_Q, 262144, 0);
    tsplit_kernel<<<dim3(16, 16, 4), tb>>>(Wk, 512, 512, 262144, WOFF_K, 262144, 0);
    conv_w_kernel<<<1024, 256>>>(Wv, WOFF_V);
    tsplit_kernel<<<dim3(64, 16, 1), tb>>>(Wc, 2048, 512, 0, WOFF_C, 0, 0);
    tsplit_kernel<<<dim3(16, 32, 1), tb>>>(W1, 512, 1024, 0, WOFF_1, 0, 1);
    tsplit_kernel<<<dim3(32, 16, 1), tb>>>(W2, 1024, 512, 0, WOFF_2, 0, 1);

    split_in_kernel<<<16384, 256>>>(x, 0);
    split_in_kernel<<<16384, 256>>>(ih, 1);
    zero_att_kernel<<<128, 256>>>();

    // M_h = Wq_h^T @ Wk_h  -> g_wM
    mma_gemm<1, 0, 0><<<dim3(4, 4, 4), 128, SMEM_P1>>>(
        4, WOFF_Q, 512, 262144, 0, WOFF_K, 262144, 512, 1, 262144, 512, nullptr);
    // P^T_h = Wc_h^T @ Wv_h^T -> g_wP
    mma_gemm<1, 0, 0><<<dim3(4, 4, 4), 128, SMEM_P1>>>(
        4, WOFF_C, 2048, 512, 0, WOFF_V, 262144, 512, 2, 262144, 512, nullptr);

    // t = ih @ M^T with fused att-dot epilogue
    mma_gemm<1, 4, 0><<<dim3(16, 256), 128, SMEM_P1>>>(
        1, 0, 512, 0, 1, 0, 0, 512, 0, 0, 0, nullptr);
    denom_kernel<<<128, 256>>>();

    // y = x @ P -> g_y bf16 [N,2048]
    mma_gemm<1, 0, 0><<<dim3(16, 256), 128, SMEM_P1>>>(
        0, 0, 512, 0, 2, 0, 0, 512, 0, 0, 2048, nullptr);

    // h1 = LN(sum_h alpha*y + x) -> fp16 planes
    ln1_fused<<<NN, 256>>>(x, lng, lnb);

    // f1 = relu(h1 @ W1 + b1) -> fp16 planes   (2-product fp16)
    mma_gemm<2, 3, 1><<<dim3(8, 256), 128, SMEM_P2>>>(
        2, 0, 512, 0, 0, WOFF_1, 0, 512, 0, 0, 1024, b1);
    // f2 = f1 @ W2 + b2 -> f32
    mma_gemm<2, 2, 1><<<dim3(4, 256), 128, SMEM_P2>>>(
        3, 0, 1024, 0, 0, WOFF_2, 0, 1024, 0, 0, 512, b2);

    ln2_kernel<<<NN, 256>>>(lng, lnb, out);
}